// round 8
// baseline (speedup 1.0000x reference)
#include <cuda_runtime.h>
#include <cuda_bf16.h>
#include <cstdint>

#define Hd 128
#define MAXM 50048
#define MAXL 400128
#define SEPS 1e-9f
#define NT 512

// ---------------- scratch (device globals; no allocations) ----------------
__device__ float g_Bx [MAXM*Hd];
__device__ float g_Wix[MAXM*Hd];
__device__ float g_Wfx[MAXM*Hd];
__device__ float g_Wox[MAXM*Hd];
__device__ float g_Wcx[MAXM*Hd];
__device__ float g_Ah [MAXM*Hd];
__device__ float g_Ufh[MAXM*Hd];
__device__ float g_hhat[MAXM*Hd];
__device__ float g_sumfc[MAXM*Hd];
__device__ float g_e[MAXL];
__device__ float g_segsum[MAXM];
__device__ unsigned g_segmax[MAXM];
// pre-split, pre-swizzled weights: 10 x 128x128 bf16 (hi & lo), 32KB each
__device__ __align__(16) char g_Wbhi[10 * 32768];
__device__ __align__(16) char g_Wblo[10 * 32768];

// ---------------- scalar helpers ----------------
__device__ __forceinline__ float sigm_f(float x) {
    return __fdividef(1.0f, 1.0f + __expf(-x));
}
__device__ __forceinline__ float tanh_f(float x) {
    float e2 = __expf(2.0f * x);
    return 1.0f - __fdividef(2.0f, e2 + 1.0f);
}
__device__ __forceinline__ unsigned encf(float f) {
    unsigned b = __float_as_uint(f);
    return (b & 0x80000000u) ? ~b : (b | 0x80000000u);
}
__device__ __forceinline__ float decf(unsigned u) {
    return (u & 0x80000000u) ? __uint_as_float(u ^ 0x80000000u) : __uint_as_float(~u);
}
__device__ __forceinline__ void red4(float* p, float x, float y, float z, float w) {
    asm volatile("red.global.add.v4.f32 [%0], {%1, %2, %3, %4};"
                 :: "l"(p), "f"(x), "f"(y), "f"(z), "f"(w) : "memory");
}
__device__ __forceinline__ uint32_t smem_u32(const void* p) {
    uint32_t a;
    asm("{ .reg .u64 t; cvta.to.shared.u64 t, %1; cvt.u32.u64 %0, t; }" : "=r"(a) : "l"(p));
    return a;
}

// ---------------- mma / ldmatrix wrappers ----------------
__device__ __forceinline__ void ldm4(uint32_t* r, uint32_t addr) {
    asm volatile("ldmatrix.sync.aligned.m8n8.x4.shared.b16 {%0,%1,%2,%3}, [%4];"
                 : "=r"(r[0]), "=r"(r[1]), "=r"(r[2]), "=r"(r[3]) : "r"(addr));
}
__device__ __forceinline__ void mma16816(float* d, const uint32_t* a, const uint32_t* b) {
    asm volatile("mma.sync.aligned.m16n8k16.row.col.f32.bf16.bf16.f32 "
                 "{%0,%1,%2,%3}, {%4,%5,%6,%7}, {%8,%9}, {%0,%1,%2,%3};"
                 : "+f"(d[0]), "+f"(d[1]), "+f"(d[2]), "+f"(d[3])
                 : "r"(a[0]), "r"(a[1]), "r"(a[2]), "r"(a[3]), "r"(b[0]), "r"(b[1]));
}

// swizzled byte offset of (row, colbyte) in a 128-row x 256B tile
__device__ __forceinline__ uint32_t swz(int row, int colbyte) {
    return (uint32_t)(row * 256 + (colbyte ^ ((row & 7) << 4)));
}
__device__ __forceinline__ void split2(float x, float y, uint32_t& hp, uint32_t& lp) {
    __nv_bfloat16 hx = __float2bfloat16(x);
    __nv_bfloat16 hy = __float2bfloat16(y);
    __nv_bfloat16 lx = __float2bfloat16(x - __bfloat162float(hx));
    __nv_bfloat16 ly = __float2bfloat16(y - __bfloat162float(hy));
    hp = ((uint32_t)__bfloat16_as_ushort(hy) << 16) | __bfloat16_as_ushort(hx);
    lp = ((uint32_t)__bfloat16_as_ushort(ly) << 16) | __bfloat16_as_ushort(lx);
}

// ---------------- prep: zero accumulators + pre-split all 10 weights ----------------
struct PrepArgs { const float* W[10]; };

__global__ void prep_kernel(PrepArgs pa, int M) {
    int stride = gridDim.x * blockDim.x;
    int gt = blockIdx.x * blockDim.x + threadIdx.x;
    int n4 = M * Hd / 4;
    float4 z = make_float4(0.f, 0.f, 0.f, 0.f);
    for (int i = gt; i < n4; i += stride) {
        ((float4*)g_hhat)[i]  = z;
        ((float4*)g_sumfc)[i] = z;
    }
    for (int i = gt; i < M; i += stride) {
        g_segsum[i] = 0.f;
        g_segmax[i] = 0u;
    }
    for (int idx = gt; idx < 10 * 8192; idx += stride) {
        int w = idx >> 13;
        int i = idx & 8191;
        int row = i >> 6;
        int c2 = i & 63;
        float2 v = *(const float2*)(pa.W[w] + (size_t)row * Hd + c2 * 2);
        uint32_t hp, lp;
        split2(v.x, v.y, hp, lp);
        uint32_t off = swz(row, c2 * 4);
        *(uint32_t*)(g_Wbhi + w * 32768 + off) = hp;
        *(uint32_t*)(g_Wblo + w * 32768 + off) = lp;
    }
}

// ---------------- shared GEMM building blocks ----------------
#define SA_HI 0
#define SA_LO 32768
#define SW_HI 65536
#define SW_LO 98304
#define S_BIAS 131072
#define S_TOT1 (131072 + 512)
// fused kernel: G gate buffer, pitch 132 floats (conflict-free)
#define S_G    131072
#define GPITCH 132
#define S_TOT3 (131072 + 128 * GPITCH * 4)

__device__ __forceinline__ void conv_tile(const float* __restrict__ A, int m0, int M,
                                          char* hi, char* lo, int tid) {
#pragma unroll
    for (int it = 0; it < 8192 / NT; it++) {
        int i = tid + it * NT;
        int row = i >> 6;
        int c2 = i & 63;
        float2 v = make_float2(0.f, 0.f);
        if (m0 + row < M) v = *(const float2*)(A + (size_t)(m0 + row) * Hd + c2 * 2);
        uint32_t hp, lp;
        split2(v.x, v.y, hp, lp);
        uint32_t off = swz(row, c2 * 4);
        *(uint32_t*)(hi + off) = hp;
        *(uint32_t*)(lo + off) = lp;
    }
}

__device__ __forceinline__ void copy_w(char* sm, const char* whi, const char* wlo, int tid) {
    const uint4* shi = (const uint4*)whi;
    const uint4* slo = (const uint4*)wlo;
#pragma unroll
    for (int it = 0; it < 2048 / NT; it++) {
        int i = tid + it * NT;
        ((uint4*)(sm + SW_HI))[i] = shi[i];
        ((uint4*)(sm + SW_LO))[i] = slo[i];
    }
}

// compute 128x128 bf16x3 gemm tile into acc[2][4][4] (per-thread fragments)
__device__ __forceinline__ void gemm_core(const uint32_t smb, float acc[2][4][4],
                                          int arow0, int akb, int brow0, int bkb) {
#pragma unroll
    for (int ti = 0; ti < 2; ti++)
#pragma unroll
        for (int tj = 0; tj < 4; tj++)
#pragma unroll
            for (int k = 0; k < 4; k++) acc[ti][tj][k] = 0.f;

#pragma unroll
    for (int ks = 0; ks < 8; ks++) {
        const int kb0 = ks * 32;
        uint32_t ah[2][4], al[2][4], bh[2][4], bl[2][4];
#pragma unroll
        for (int ti = 0; ti < 2; ti++) {
            int row = arow0 + ti * 16;
            uint32_t off = swz(row, kb0 + akb);
            ldm4(ah[ti], smb + SA_HI + off);
            ldm4(al[ti], smb + SA_LO + off);
        }
#pragma unroll
        for (int tp = 0; tp < 2; tp++) {
            int row = brow0 + tp * 16;
            uint32_t off = swz(row, kb0 + bkb);
            ldm4(bh[tp], smb + SW_HI + off);
            ldm4(bl[tp], smb + SW_LO + off);
        }
#pragma unroll
        for (int ti = 0; ti < 2; ti++)
#pragma unroll
            for (int tj = 0; tj < 4; tj++) {
                const uint32_t* bhp = &bh[tj >> 1][(tj & 1) * 2];
                const uint32_t* blp = &bl[tj >> 1][(tj & 1) * 2];
                mma16816(acc[ti][tj], ah[ti], bhp);
                mma16816(acc[ti][tj], ah[ti], blp);
                mma16816(acc[ti][tj], al[ti], bhp);
            }
    }
}

// ---------------- phase-1 GEMM: 7 weights, plain C outputs ----------------
struct TcArgs {
    const float* A1;
    const float* A2;
    const char* whi[7];
    const char* wlo[7];
    const float* b[7];
    float* C[7];
    int nW1, nW2, M;
};

__global__ void __launch_bounds__(NT, 1) gemm_mma(TcArgs ga) {
    extern __shared__ char sm[];
    const uint32_t smb = smem_u32(sm);
    const int tid = threadIdx.x;
    const int wid = tid >> 5;
    const int lane = tid & 31;
    const int m0 = blockIdx.x * 128;
    const int M = ga.M;
    const int wm = wid >> 2;
    const int wn = wid & 3;
    const int sub = lane & 7;
    const int quad = lane >> 3;
    const int arow0 = wm * 32 + sub + (quad & 1) * 8;
    const int akb   = (quad >> 1) * 16;
    const int brow0 = wn * 32 + sub + (quad >> 1) * 8;
    const int bkb   = (quad & 1) * 16;

    const float* Acur = ga.A1;
    int nW = ga.nW1;
    int wbase = 0;

    for (int sec = 0; sec < 2; sec++) {
        if (nW == 0) break;
        __syncthreads();
        conv_tile(Acur, m0, M, sm + SA_HI, sm + SA_LO, tid);

        for (int wi = 0; wi < nW; wi++) {
            const int w = wbase + wi;
            __syncthreads();
            copy_w(sm, ga.whi[w], ga.wlo[w], tid);
            if (tid < 128) ((float*)(sm + S_BIAS))[tid] = ga.b[w] ? __ldg(ga.b[w] + tid) : 0.f;
            __syncthreads();

            float acc[2][4][4];
            gemm_core(smb, acc, arow0, akb, brow0, bkb);

            const int g = lane >> 2;
            const int tg = lane & 3;
            float* __restrict__ C = ga.C[w];
            const float* sb = (const float*)(sm + S_BIAS);
#pragma unroll
            for (int ti = 0; ti < 2; ti++)
#pragma unroll
                for (int tj = 0; tj < 4; tj++) {
                    int row = m0 + wm * 32 + ti * 16 + g;
                    int col = wn * 32 + tj * 8 + tg * 2;
                    float2 bv = *(const float2*)(sb + col);
                    if (row < M)
                        *(float2*)(C + (size_t)row * Hd + col) =
                            make_float2(acc[ti][tj][0] + bv.x, acc[ti][tj][1] + bv.y);
                    if (row + 8 < M)
                        *(float2*)(C + (size_t)(row + 8) * Hd + col) =
                            make_float2(acc[ti][tj][2] + bv.x, acc[ti][tj][3] + bv.y);
                }
        }
        wbase += nW;
        Acur = ga.A2;
        nW = ga.nW2;
    }
}

// ---------------- phase-3 fused GEMM + gates ----------------
// W sequence: Ui, Uc, Uo on A = hhat. Gates use Wix/Wcx/Wox (bias already in) + sumfc.
struct FusedArgs {
    const char* whi[3];
    const char* wlo[3];
    float* outh;
    float* outc;
    int M;
};

__global__ void __launch_bounds__(NT, 1) gemm_fused3(FusedArgs fa) {
    extern __shared__ char sm[];
    const uint32_t smb = smem_u32(sm);
    float* G = (float*)(sm + S_G);
    const int tid = threadIdx.x;
    const int wid = tid >> 5;
    const int lane = tid & 31;
    const int m0 = blockIdx.x * 128;
    const int M = fa.M;
    const int wm = wid >> 2;
    const int wn = wid & 3;
    const int sub = lane & 7;
    const int quad = lane >> 3;
    const int arow0 = wm * 32 + sub + (quad & 1) * 8;
    const int akb   = (quad >> 1) * 16;
    const int brow0 = wn * 32 + sub + (quad >> 1) * 8;
    const int bkb   = (quad & 1) * 16;
    const int g = lane >> 2;
    const int tg = lane & 3;

    conv_tile(g_hhat, m0, M, sm + SA_HI, sm + SA_LO, tid);

    for (int w = 0; w < 3; w++) {
        __syncthreads();
        copy_w(sm, fa.whi[w], fa.wlo[w], tid);
        __syncthreads();

        float acc[2][4][4];
        gemm_core(smb, acc, arow0, akb, brow0, bkb);

#pragma unroll
        for (int ti = 0; ti < 2; ti++)
#pragma unroll
            for (int tj = 0; tj < 4; tj++) {
                int rl = wm * 32 + ti * 16 + g;          // local row
                int col = wn * 32 + tj * 8 + tg * 2;
#pragma unroll
                for (int half = 0; half < 2; half++) {
                    int row = m0 + rl + half * 8;
                    float u0 = acc[ti][tj][half * 2 + 0];
                    float u1 = acc[ti][tj][half * 2 + 1];
                    size_t go = (size_t)row * Hd + col;
                    int gi = (rl + half * 8) * GPITCH + col;
                    if (w == 0) {
                        float2 wx = row < M ? *(const float2*)(g_Wix + go)
                                            : make_float2(0.f, 0.f);
                        G[gi + 0] = sigm_f(wx.x + u0);
                        G[gi + 1] = sigm_f(wx.y + u1);
                    } else if (w == 1) {
                        float2 wx = row < M ? *(const float2*)(g_Wcx + go)
                                            : make_float2(0.f, 0.f);
                        float2 sf = row < M ? *(const float2*)(g_sumfc + go)
                                            : make_float2(0.f, 0.f);
                        float c0 = fmaf(G[gi + 0], tanh_f(wx.x + u0), sf.x);
                        float c1 = fmaf(G[gi + 1], tanh_f(wx.y + u1), sf.y);
                        if (row < M)
                            *(float2*)(fa.outc + go) = make_float2(c0, c1);
                        G[gi + 0] = tanh_f(c0);
                        G[gi + 1] = tanh_f(c1);
                    } else {
                        float2 wx = row < M ? *(const float2*)(g_Wox + go)
                                            : make_float2(0.f, 0.f);
                        float h0 = sigm_f(wx.x + u0) * G[gi + 0];
                        float h1 = sigm_f(wx.y + u1) * G[gi + 1];
                        if (row < M)
                            *(float2*)(fa.outh + go) = make_float2(h0, h1);
                    }
                }
            }
    }
}

// ---------------- pair pass 1 ----------------
__global__ void pair_e_kernel(const int* __restrict__ ci, const int* __restrict__ chi,
                              const float* __restrict__ v, int L) {
    __shared__ float vs[Hd];
    if (threadIdx.x < Hd) vs[threadIdx.x] = v[threadIdx.x];
    __syncthreads();

    int w = blockIdx.x * (blockDim.x >> 5) + (threadIdx.x >> 5);
    int lane = threadIdx.x & 31;
    if (w >= L) return;

    int c  = __ldg(ci + w);
    int ch = __ldg(chi + w);
    float4 a  = *(const float4*)(g_Ah + (size_t)ch * Hd + lane * 4);
    float4 b  = *(const float4*)(g_Bx + (size_t)c * Hd + lane * 4);
    float4 vv = *(const float4*)(vs + lane * 4);

    float s = tanh_f(a.x + b.x) * vv.x + tanh_f(a.y + b.y) * vv.y +
              tanh_f(a.z + b.z) * vv.z + tanh_f(a.w + b.w) * vv.w;
#pragma unroll
    for (int o = 16; o; o >>= 1) s += __shfl_xor_sync(0xFFFFFFFFu, s, o);

    if (lane == 0) {
        g_e[w] = s;
        atomicMax(g_segmax + c, encf(s));
    }
}

// ---------------- pair pass 2 ----------------
__global__ void pair_exp_kernel(const int* __restrict__ ci, int L) {
    int l = blockIdx.x * blockDim.x + threadIdx.x;
    if (l >= L) return;
    int c = ci[l];
    float mx = decf(g_segmax[c]);
    float xe = __expf(g_e[l] - mx);
    g_e[l] = xe;
    atomicAdd(g_segsum + c, xe);
}

// ---------------- pair pass 3 ----------------
__global__ void pair_acc_kernel(const float* __restrict__ child_h,
                                const float* __restrict__ child_c,
                                const int* __restrict__ ci, const int* __restrict__ chi,
                                int L) {
    int w = blockIdx.x * (blockDim.x >> 5) + (threadIdx.x >> 5);
    int lane = threadIdx.x & 31;
    if (w >= L) return;

    int c  = __ldg(ci + w);
    int ch = __ldg(chi + w);
    float attn = __ldg(g_e + w) / (__ldg(g_segsum + c) + SEPS);

    size_t co  = (size_t)c * Hd + lane * 4;
    size_t cho = (size_t)ch * Hd + lane * 4;

    float4 hv = *(const float4*)(child_h + cho);
    red4(g_hhat + co, attn * hv.x, attn * hv.y, attn * hv.z, attn * hv.w);

    float4 wf = *(const float4*)(g_Wfx + co);
    float4 uf = *(const float4*)(g_Ufh + cho);
    float4 cv = *(const float4*)(child_c + cho);
    float fx = sigm_f(wf.x + uf.x) * cv.x;
    float fy = sigm_f(wf.y + uf.y) * cv.y;
    float fz = sigm_f(wf.z + uf.z) * cv.z;
    float fw = sigm_f(wf.w + uf.w) * cv.w;
    red4(g_sumfc + co, fx, fy, fz, fw);
}

// ---------------- launch ----------------
extern "C" void kernel_launch(void* const* d_in, const int* in_sizes, int n_in,
                              void* d_out, int out_size) {
    const float* x_emb   = (const float*)d_in[0];
    const float* child_h = (const float*)d_in[1];
    const float* child_c = (const float*)d_in[2];
    const int*   ci      = (const int*)d_in[3];
    const int*   chi     = (const int*)d_in[4];
    const float* Wi_w = (const float*)d_in[5];
    const float* Ui_w = (const float*)d_in[6];
    const float* Wf_w = (const float*)d_in[7];
    const float* Uf_w = (const float*)d_in[8];
    const float* Wo_w = (const float*)d_in[9];
    const float* Uo_w = (const float*)d_in[10];
    const float* Wc_w = (const float*)d_in[11];
    const float* Uc_w = (const float*)d_in[12];
    const float* Wa_w = (const float*)d_in[13];
    const float* Ua_w = (const float*)d_in[14];
    const float* Wi_b = (const float*)d_in[15];
    const float* Wf_b = (const float*)d_in[16];
    const float* Wo_b = (const float*)d_in[17];
    const float* Wc_b = (const float*)d_in[18];
    const float* Wa_b = (const float*)d_in[19];
    const float* v_w  = (const float*)d_in[20];

    const int M = in_sizes[0] / Hd;
    const int L = in_sizes[3];

    float *p_Bx, *p_Wix, *p_Wfx, *p_Wox, *p_Wcx, *p_Ah, *p_Ufh;
    cudaGetSymbolAddress((void**)&p_Bx,  g_Bx);
    cudaGetSymbolAddress((void**)&p_Wix, g_Wix);
    cudaGetSymbolAddress((void**)&p_Wfx, g_Wfx);
    cudaGetSymbolAddress((void**)&p_Wox, g_Wox);
    cudaGetSymbolAddress((void**)&p_Wcx, g_Wcx);
    cudaGetSymbolAddress((void**)&p_Ah,  g_Ah);
    cudaGetSymbolAddress((void**)&p_Ufh, g_Ufh);
    char *p_whi, *p_wlo;
    cudaGetSymbolAddress((void**)&p_whi, g_Wbhi);
    cudaGetSymbolAddress((void**)&p_wlo, g_Wblo);

    float* outh = (float*)d_out;
    float* outc = outh + (size_t)M * Hd;

    const int mtiles = (M + 127) / 128;

    cudaFuncSetAttribute(gemm_mma, cudaFuncAttributeMaxDynamicSharedMemorySize, S_TOT1);
    cudaFuncSetAttribute(gemm_fused3, cudaFuncAttributeMaxDynamicSharedMemorySize, S_TOT3);

    // weight order in g_Wb: 0:Ua 1:Wi 2:Wf 3:Wo 4:Wc 5:Wa 6:Uf 7:Ui 8:Uc 9:Uo
    {
        PrepArgs pa;
        pa.W[0] = Ua_w; pa.W[1] = Wi_w; pa.W[2] = Wf_w; pa.W[3] = Wo_w; pa.W[4] = Wc_w;
        pa.W[5] = Wa_w; pa.W[6] = Uf_w; pa.W[7] = Ui_w; pa.W[8] = Uc_w; pa.W[9] = Uo_w;
        prep_kernel<<<296, 256>>>(pa, M);
    }

    // phase 1: x-side (Bx, Wix, Wfx, Wox, Wcx) + child_h-side (Ah, Ufh)
    {
        TcArgs ga;
        ga.A1 = x_emb; ga.A2 = child_h; ga.nW1 = 5; ga.nW2 = 2; ga.M = M;
        int slot[7] = {0, 1, 2, 3, 4, 5, 6};
        const float* bs[7] = {nullptr, Wi_b, Wf_b, Wo_b, Wc_b, Wa_b, nullptr};
        float* cs[7] = {p_Bx, p_Wix, p_Wfx, p_Wox, p_Wcx, p_Ah, p_Ufh};
        for (int i = 0; i < 7; i++) {
            ga.whi[i] = p_whi + slot[i] * 32768;
            ga.wlo[i] = p_wlo + slot[i] * 32768;
            ga.b[i] = bs[i];
            ga.C[i] = cs[i];
        }
        gemm_mma<<<mtiles, NT, S_TOT1>>>(ga);
    }

    // attention + forget-gate pair passes
    pair_e_kernel<<<(L + 7) / 8, 256>>>(ci, chi, v_w, L);
    pair_exp_kernel<<<(L + 255) / 256, 256>>>(ci, L);
    pair_acc_kernel<<<(L + 7) / 8, 256>>>(child_h, child_c, ci, chi, L);

    // phase 3: fused h_hat GEMMs (Ui, Uc, Uo) + gate epilogue -> outh/outc
    {
        FusedArgs fa;
        int slot[3] = {7, 8, 9};
        for (int i = 0; i < 3; i++) {
            fa.whi[i] = p_whi + slot[i] * 32768;
            fa.wlo[i] = p_wlo + slot[i] * 32768;
        }
        fa.outh = outh; fa.outc = outc; fa.M = M;
        gemm_fused3<<<mtiles, NT, S_TOT3>>>(fa);
    }
}